// round 2
// baseline (speedup 1.0000x reference)
#include <cuda_runtime.h>
#include <cstdint>

typedef unsigned long long ull;

// Problem dims (fixed for this problem instance)
static constexpr int B_   = 1024;
static constexpr int T_   = 512;
static constexpr int DIN  = 128;
static constexpr int H_   = 64;
static constexpr int O_   = 20;

// Scratch: precomputed layer-1 currents, layout [b*T + t][64]
__device__ float g_cur1[(size_t)B_ * T_ * H_];

// ---------------------------------------------------------------------------
// packed f32x2 helpers (sm_103a)
// ---------------------------------------------------------------------------
__device__ __forceinline__ ull ffma2(ull a, ull b, ull c) {
    ull d;
    asm("fma.rn.f32x2 %0, %1, %2, %3;" : "=l"(d) : "l"(a), "l"(b), "l"(c));
    return d;
}
__device__ __forceinline__ ull pack2(float x, float y) {
    ull d;
    asm("mov.b64 %0, {%1,%2};" : "=l"(d) : "f"(x), "f"(y));
    return d;
}
__device__ __forceinline__ float2 unpack2(ull v) {
    float2 r;
    asm("mov.b64 {%0,%1}, %2;" : "=f"(r.x), "=f"(r.y) : "l"(v));
    return r;
}

// ---------------------------------------------------------------------------
// Kernel 1: cur1[r][n] = sum_k x[r][k] * W1[n][k] + b1[n]
// r in [0, B*T), k in [0,128), n in [0,64)
// Tiles: 64 rows x 64 cols per block, K in 2 chunks of 64.
// 128 threads, each computes 4(m) x 8(n) outputs with packed f32x2 FMA.
// ---------------------------------------------------------------------------
__global__ void __launch_bounds__(128) snn_gemm1(
    const float* __restrict__ x,
    const float* __restrict__ W1,
    const float* __restrict__ b1)
{
    constexpr int BM = 64;
    constexpr int KC = 64;
    constexpr int SP = BM + 4;           // padded stride (floats)

    __shared__ float Xs[KC][SP];         // [k][m]
    __shared__ float Ws[KC][SP];         // [k][n]

    const int tid   = threadIdx.x;
    const int rbase = blockIdx.x * BM;
    const int m0    = (tid & 15) * 4;    // 0..60 step 4
    const int n0    = (tid >> 4) * 8;    // 0..56 step 8

    ull acc[4][4];
#pragma unroll
    for (int i = 0; i < 4; i++)
#pragma unroll
        for (int j = 0; j < 4; j++) acc[i][j] = pack2(0.f, 0.f);

    for (int c = 0; c < 2; c++) {
        const int k0 = c * KC;
        // --- load tiles (transposed into [k][m]/[k][n]) ---
#pragma unroll
        for (int p = 0; p < 8; p++) {
            int idx = p * 128 + tid;         // 0..1023
            int row = idx >> 4;              // 0..63
            int f   = idx & 15;              // 0..15 (float4 index along k)
            float4 v = *reinterpret_cast<const float4*>(
                x + (size_t)(rbase + row) * DIN + k0 + f * 4);
            Xs[f * 4 + 0][row] = v.x;
            Xs[f * 4 + 1][row] = v.y;
            Xs[f * 4 + 2][row] = v.z;
            Xs[f * 4 + 3][row] = v.w;
            float4 w = *reinterpret_cast<const float4*>(
                W1 + (size_t)row * DIN + k0 + f * 4);
            Ws[f * 4 + 0][row] = w.x;
            Ws[f * 4 + 1][row] = w.y;
            Ws[f * 4 + 2][row] = w.z;
            Ws[f * 4 + 3][row] = w.w;
        }
        __syncthreads();

        // --- compute ---
#pragma unroll 8
        for (int kk = 0; kk < KC; kk++) {
            float4 a4 = *reinterpret_cast<const float4*>(&Xs[kk][m0]);
            const ull* wp = reinterpret_cast<const ull*>(&Ws[kk][n0]);
            ull w0 = wp[0], w1 = wp[1], w2 = wp[2], w3 = wp[3];
            ull a0 = pack2(a4.x, a4.x);
            ull a1 = pack2(a4.y, a4.y);
            ull a2 = pack2(a4.z, a4.z);
            ull a3 = pack2(a4.w, a4.w);
            acc[0][0] = ffma2(a0, w0, acc[0][0]);
            acc[0][1] = ffma2(a0, w1, acc[0][1]);
            acc[0][2] = ffma2(a0, w2, acc[0][2]);
            acc[0][3] = ffma2(a0, w3, acc[0][3]);
            acc[1][0] = ffma2(a1, w0, acc[1][0]);
            acc[1][1] = ffma2(a1, w1, acc[1][1]);
            acc[1][2] = ffma2(a1, w2, acc[1][2]);
            acc[1][3] = ffma2(a1, w3, acc[1][3]);
            acc[2][0] = ffma2(a2, w0, acc[2][0]);
            acc[2][1] = ffma2(a2, w1, acc[2][1]);
            acc[2][2] = ffma2(a2, w2, acc[2][2]);
            acc[2][3] = ffma2(a2, w3, acc[2][3]);
            acc[3][0] = ffma2(a3, w0, acc[3][0]);
            acc[3][1] = ffma2(a3, w1, acc[3][1]);
            acc[3][2] = ffma2(a3, w2, acc[3][2]);
            acc[3][3] = ffma2(a3, w3, acc[3][3]);
        }
        __syncthreads();
    }

    // --- epilogue: add bias, store ---
    float bias[8];
#pragma unroll
    for (int j = 0; j < 8; j++) bias[j] = __ldg(b1 + n0 + j);

#pragma unroll
    for (int i = 0; i < 4; i++) {
        float2 p0 = unpack2(acc[i][0]);
        float2 p1 = unpack2(acc[i][1]);
        float2 p2 = unpack2(acc[i][2]);
        float2 p3 = unpack2(acc[i][3]);
        float4 o0 = make_float4(p0.x + bias[0], p0.y + bias[1],
                                p1.x + bias[2], p1.y + bias[3]);
        float4 o1 = make_float4(p2.x + bias[4], p2.y + bias[5],
                                p3.x + bias[6], p3.y + bias[7]);
        float* dst = g_cur1 + (size_t)(rbase + m0 + i) * H_ + n0;
        *reinterpret_cast<float4*>(dst)     = o0;
        *reinterpret_cast<float4*>(dst + 4) = o1;
    }
}

// ---------------------------------------------------------------------------
// Kernel 2: the recurrent scan. One warp per batch element.
// Lane L owns neurons L and L+32 of layers 1/2; lanes 0..19 own layer-3.
// Spike masks via ballots; layer-2/3 matvecs as sparse bit-driven column sums.
// ---------------------------------------------------------------------------
__device__ __forceinline__ float clip01(float v) {
    return fminf(fmaxf(v, 0.f), 1.f);
}

__global__ void __launch_bounds__(32) snn_scan(
    const float* __restrict__ W2, const float* __restrict__ b2,
    const float* __restrict__ beta2,
    const float* __restrict__ W3, const float* __restrict__ b3,
    const float* __restrict__ beta3,
    const float* __restrict__ beta1,
    float* __restrict__ out)
{
    __shared__ float sW2T[64 * 64];   // [i][j] = W2[j][i]
    __shared__ float sW3T[64 * 32];   // [i][o] = W3[o][i], padded, junk cols = 0

    const int lane = threadIdx.x;
    const int b    = blockIdx.x;

    // load transposed weights
    for (int idx = lane; idx < 64 * 64; idx += 32) {
        int j = idx >> 6, i = idx & 63;
        sW2T[i * 64 + j] = W2[idx];
    }
    for (int idx = lane; idx < 64 * 32; idx += 32) sW3T[idx] = 0.f;
    __syncwarp();
    for (int idx = lane; idx < O_ * 64; idx += 32) {
        int o = idx >> 6, i = idx & 63;
        sW3T[i * 32 + o] = W3[idx];
    }
    __syncwarp();

    // per-lane constants
    const float bt1a = clip01(beta1[lane]);
    const float bt1b = clip01(beta1[lane + 32]);
    const float bt2a = clip01(beta2[lane]);
    const float bt2b = clip01(beta2[lane + 32]);
    const float b2a  = b2[lane];
    const float b2b  = b2[lane + 32];
    const float bt3  = (lane < O_) ? clip01(beta3[lane]) : 0.f;
    const float b3v  = (lane < O_) ? b3[lane] : 0.f;

    float m1a = 0.f, m1b = 0.f, m2a = 0.f, m2b = 0.f, m3 = 0.f;

    const float* src = g_cur1 + (size_t)b * T_ * H_ + lane;
    float* dst       = out + (size_t)b * T_ * O_;

    constexpr int PD = 8;          // prefetch depth
    float pa[PD], pb[PD];
#pragma unroll
    for (int i = 0; i < PD; i++) {
        pa[i] = src[i * H_];
        pb[i] = src[i * H_ + 32];
    }

#pragma unroll 8
    for (int t = 0; t < T_; t++) {
        const int slot = t & (PD - 1);
        const float ca = pa[slot];
        const float cb = pb[slot];
        const int tn = t + PD;
        if (tn < T_) {
            pa[slot] = src[(size_t)tn * H_];
            pb[slot] = src[(size_t)tn * H_ + 32];
        }

        // layer 1: subtract-reset leaky + spike
        float r;
        r   = (m1a > 1.f) ? 1.f : 0.f;
        m1a = bt1a * m1a + ca - r;
        r   = (m1b > 1.f) ? 1.f : 0.f;
        m1b = bt1b * m1b + cb - r;
        unsigned lo = __ballot_sync(0xffffffffu, m1a > 1.f);
        unsigned hi = __ballot_sync(0xffffffffu, m1b > 1.f);
        ull mk = (ull)lo | ((ull)hi << 32);

        // layer 2 current: sparse column-sum of W2^T (mask uniform over warp)
        float acc_a = b2a, acc_b = b2b;
        while (mk) {
            int i = __ffsll((long long)mk) - 1;
            mk &= mk - 1;
            acc_a += sW2T[(i << 6) + lane];
            acc_b += sW2T[(i << 6) + lane + 32];
        }

        r   = (m2a > 1.f) ? 1.f : 0.f;
        m2a = bt2a * m2a + acc_a - r;
        r   = (m2b > 1.f) ? 1.f : 0.f;
        m2b = bt2b * m2b + acc_b - r;
        lo = __ballot_sync(0xffffffffu, m2a > 1.f);
        hi = __ballot_sync(0xffffffffu, m2b > 1.f);
        mk = (ull)lo | ((ull)hi << 32);

        // layer 3 current (no reset): sparse sum of W3^T columns
        float acc3 = b3v;
        while (mk) {
            int i = __ffsll((long long)mk) - 1;
            mk &= mk - 1;
            acc3 += sW3T[(i << 5) + lane];   // junk (0) for lane >= 20
        }
        m3 = bt3 * m3 + acc3;

        if (lane < O_) dst[(size_t)t * O_ + lane] = m3;
    }
}

// ---------------------------------------------------------------------------
// Launch
// ---------------------------------------------------------------------------
extern "C" void kernel_launch(void* const* d_in, const int* in_sizes, int n_in,
                              void* d_out, int out_size)
{
    const float* x     = (const float*)d_in[0];
    const float* W1    = (const float*)d_in[1];
    const float* b1    = (const float*)d_in[2];
    const float* beta1 = (const float*)d_in[3];
    const float* W2    = (const float*)d_in[4];
    const float* b2    = (const float*)d_in[5];
    const float* beta2 = (const float*)d_in[6];
    const float* W3    = (const float*)d_in[7];
    const float* b3    = (const float*)d_in[8];
    const float* beta3 = (const float*)d_in[9];
    float* out = (float*)d_out;

    const int R = in_sizes[0] / DIN;     // B*T = 524288

    snn_gemm1<<<R / 64, 128>>>(x, W1, b1);
    snn_scan<<<B_, 32>>>(W2, b2, beta2, W3, b3, beta3, beta1, out);
}